// round 13
// baseline (speedup 1.0000x reference)
#include <cuda_runtime.h>
#include <cuda_bf16.h>
#include <cstdint>

// Problem constants
#define B_     2
#define L2_    4
#define N2_    2048
#define L1_    9
#define N1_    8192
#define CIN_   128
#define CT_    128
#define CS_    256
#define CORIG_ 64
#define KD3_   192   // CT_ + CORIG_

typedef __nv_bfloat16 bf16;

// Scratch (static device globals — no runtime allocation)
__device__ float g_tt [B_*L2_*3*N2_*CT_];                 // stage-2 out, n-major [z][n][o] fp32
__device__ __align__(128) float4 g_ssort[8*N2_];          // cell-sorted seeds (x,y,z,|s|^2)
__device__ __align__(128) int    g_sidx [8*N2_];          // original seed index per sorted slot
__device__ __align__(128) float4 g_gmeta[8*64*2];         // per-32-seed-block AABB lo/hi
__device__ __align__(128) float4 g_qsort[18*N1_];         // cell-sorted queries (x,y,z,qid)
__device__ __align__(128) bf16 g_wt0h[3*CT_*CIN_];
__device__ __align__(128) bf16 g_wt0l[3*CT_*CIN_];
__device__ __align__(128) bf16 g_wt1h[3*CT_*CT_];
__device__ __align__(128) bf16 g_wt1l[3*CT_*CT_];
__device__ __align__(128) bf16 g_whi [CS_*KD3_];
__device__ __align__(128) bf16 g_wlo [CS_*KD3_];
__device__ __align__(128) bf16 g_fh  [(size_t)B_*L2_*CIN_*N2_];
__device__ __align__(128) bf16 g_fl  [(size_t)B_*L2_*CIN_*N2_];
__device__ __align__(128) bf16 g_bhi [(size_t)B_*L1_*N1_*KD3_];
__device__ __align__(128) bf16 g_blo [(size_t)B_*L1_*N1_*KD3_];

__device__ __forceinline__ uint32_t smem_u32(const void* p) {
    uint32_t a;
    asm("{ .reg .u64 t; cvta.to.shared.u64 t, %1; cvt.u32.u64 %0, t; }"
        : "=r"(a) : "l"(p));
    return a;
}
__device__ __forceinline__ void ldmx4(uint32_t* r, uint32_t addr) {
    asm volatile("ldmatrix.sync.aligned.m8n8.x4.shared.b16 {%0,%1,%2,%3}, [%4];"
                 : "=r"(r[0]), "=r"(r[1]), "=r"(r[2]), "=r"(r[3]) : "r"(addr));
}
__device__ __forceinline__ void ldmx4t(uint32_t* r, uint32_t addr) {
    asm volatile("ldmatrix.sync.aligned.m8n8.x4.trans.shared.b16 {%0,%1,%2,%3}, [%4];"
                 : "=r"(r[0]), "=r"(r[1]), "=r"(r[2]), "=r"(r[3]) : "r"(addr));
}
__device__ __forceinline__ void mma_bf16(float* d, const uint32_t* a,
                                         const uint32_t* b) {
    asm volatile("mma.sync.aligned.m16n8k16.row.col.f32.bf16.bf16.f32 "
                 "{%0,%1,%2,%3}, {%4,%5,%6,%7}, {%8,%9}, {%0,%1,%2,%3};"
                 : "+f"(d[0]), "+f"(d[1]), "+f"(d[2]), "+f"(d[3])
                 : "r"(a[0]), "r"(a[1]), "r"(a[2]), "r"(a[3]),
                   "r"(b[0]), "r"(b[1]));
}
__device__ __forceinline__ void split_bf16(float v, bf16& hi, bf16& lo) {
    hi = __float2bfloat16(v);
    lo = __float2bfloat16(v - __bfloat162float(hi));
}
__device__ __forceinline__ void cpa16(uint32_t saddr, const void* g) {
    asm volatile("cp.async.cg.shared.global [%0], [%1], 16;"
                 :: "r"(saddr), "l"(g));
}
#define CPA_COMMIT() asm volatile("cp.async.commit_group;" ::: "memory")
#define CPA_WAIT(n)  asm volatile("cp.async.wait_group %0;" :: "n"(n) : "memory")

__device__ __forceinline__ int mpart(int v) {      // 3-bit spread to bits 0,3,6
    return (v & 1) | ((v & 2) << 2) | ((v & 4) << 4);
}
__device__ __forceinline__ int cell_id(float x, float y, float z) {
    int cx = min(7, max(0, (int)floorf(x) + 4));
    int cy = min(7, max(0, (int)floorf(y) + 4));
    int cz = min(7, max(0, (int)floorf(z) + 4));
    return (mpart(cx) << 2) | (mpart(cy) << 1) | mpart(cz);
}

// ---------------------------------------------------------------------------
// Prep: weight/feature/OF splits + seed sort (+AABBs) + query sort
// ---------------------------------------------------------------------------
#define PREP_W   576
#define PREP_F   8192
#define PREP_OF  2304
#define PREP_SS  8
#define PREP_SQ  18
__global__ __launch_bounds__(256) void k_prep(
    const float* __restrict__ Wt0, const float* __restrict__ Wt1,
    const float* __restrict__ Ws,  const float* __restrict__ F,
    const float* __restrict__ OF,  const float* __restrict__ xyzs,
    const float* __restrict__ oxyzs)
{
    __shared__ __align__(16) char sbuf[20992];
    const int bx  = blockIdx.x;
    const int tid = threadIdx.x;
    if (bx < PREP_W) {
        int i = bx * 256 + tid;
        bf16 hi, lo;
        if (i < 49152) {
            split_bf16(Wt0[i], hi, lo);
            g_wt0h[i] = hi; g_wt0l[i] = lo;
        } else if (i < 98304) {
            int j = i - 49152;
            split_bf16(Wt1[j], hi, lo);
            g_wt1h[j] = hi; g_wt1l[j] = lo;
        } else {
            int j = i - 98304;
            split_bf16(Ws[j], hi, lo);
            g_whi[j] = hi; g_wlo[j] = lo;
        }
    } else if (bx < PREP_W + PREP_F) {
        size_t i = (size_t)(bx - PREP_W) * 256 + tid;
        bf16 hi, lo;
        split_bf16(F[i], hi, lo);
        g_fh[i] = hi; g_fl[i] = lo;
    } else if (bx < PREP_W + PREP_F + PREP_OF) {
        const int rb = bx - PREP_W - PREP_F;
        const int bt = rb >> 7;
        const int nb = (rb & 127) * 64;
        bf16 (*sh)[65] = (bf16(*)[65])sbuf;
        bf16 (*sl)[65] = (bf16(*)[65])(sbuf + 64 * 65 * 2);
#pragma unroll
        for (int i = 0; i < 16; i++) {
            int idx = tid + i * 256;
            int c = idx >> 6, n = idx & 63;
            bf16 hi, lo;
            split_bf16(OF[((size_t)bt * CORIG_ + c) * N1_ + nb + n], hi, lo);
            sh[c][n] = hi; sl[c][n] = lo;
        }
        __syncthreads();
#pragma unroll
        for (int i = 0; i < 16; i++) {
            int idx = tid + i * 256;
            int n = idx >> 6, c = idx & 63;
            size_t d = ((size_t)bt * N1_ + nb + n) * KD3_ + CT_ + c;
            g_bhi[d] = sh[c][n];
            g_blo[d] = sl[c][n];
        }
    } else if (bx < PREP_W + PREP_F + PREP_OF + PREP_SS) {
        // ---- seed counting sort by Morton cell + per-block AABBs ----
        const int set = bx - PREP_W - PREP_F - PREP_OF;   // 0..7 = bq*4+t2
        int* cids = (int*)sbuf;              // 2048
        int* hist = (int*)(sbuf + 8192);     // 512
        int* part = (int*)(sbuf + 10240);    // 256
        const float* sp = xyzs + (size_t)set * N2_ * 3;
        hist[tid] = 0; hist[tid + 256] = 0;
        __syncthreads();
#pragma unroll
        for (int k = 0; k < 8; k++) {
            int i = tid + k * 256;
            int cid = cell_id(sp[3 * i], sp[3 * i + 1], sp[3 * i + 2]);
            cids[i] = cid;
            atomicAdd(&hist[cid], 1);
        }
        __syncthreads();
        int a = hist[2 * tid], b = hist[2 * tid + 1];
        int s = a + b;
        part[tid] = s;
        __syncthreads();
        for (int off = 1; off < 256; off <<= 1) {
            int v = (tid >= off) ? part[tid - off] : 0;
            __syncthreads();
            part[tid] += v;
            __syncthreads();
        }
        int excl = part[tid] - s;
        hist[2 * tid]     = excl;
        hist[2 * tid + 1] = excl + a;
        __syncthreads();
#pragma unroll
        for (int k = 0; k < 8; k++) {
            int i = tid + k * 256;
            int r = atomicAdd(&hist[cids[i]], 1);
            float x = sp[3 * i], y = sp[3 * i + 1], z = sp[3 * i + 2];
            g_ssort[set * N2_ + r] =
                make_float4(x, y, z, x * x + y * y + z * z);
            g_sidx[set * N2_ + r] = i;
        }
        __syncthreads();
        if (tid < 64) {
            float lx = 3.4e38f, ly = 3.4e38f, lz = 3.4e38f;
            float hx = -3.4e38f, hy = -3.4e38f, hz = -3.4e38f;
#pragma unroll 4
            for (int t = 0; t < 32; t++) {
                float4 v = g_ssort[set * N2_ + tid * 32 + t];
                lx = fminf(lx, v.x); hx = fmaxf(hx, v.x);
                ly = fminf(ly, v.y); hy = fmaxf(hy, v.y);
                lz = fminf(lz, v.z); hz = fmaxf(hz, v.z);
            }
            g_gmeta[(set * 64 + tid) * 2]     = make_float4(lx, ly, lz, 0.f);
            g_gmeta[(set * 64 + tid) * 2 + 1] = make_float4(hx, hy, hz, 0.f);
        }
    } else {
        // ---- query counting sort by Morton cell ----
        const int bt = bx - PREP_W - PREP_F - PREP_OF - PREP_SS;  // 0..17
        short* cids = (short*)sbuf;          // 8192
        int*   hist = (int*)(sbuf + 16384);  // 512
        int*   part = (int*)(sbuf + 18432);  // 256
        const float* qp = oxyzs + (size_t)bt * N1_ * 3;
        hist[tid] = 0; hist[tid + 256] = 0;
        __syncthreads();
#pragma unroll
        for (int k = 0; k < 32; k++) {
            int i = tid + k * 256;
            int cid = cell_id(qp[3 * i], qp[3 * i + 1], qp[3 * i + 2]);
            cids[i] = (short)cid;
            atomicAdd(&hist[cid], 1);
        }
        __syncthreads();
        int a = hist[2 * tid], b = hist[2 * tid + 1];
        int s = a + b;
        part[tid] = s;
        __syncthreads();
        for (int off = 1; off < 256; off <<= 1) {
            int v = (tid >= off) ? part[tid - off] : 0;
            __syncthreads();
            part[tid] += v;
            __syncthreads();
        }
        int excl = part[tid] - s;
        hist[2 * tid]     = excl;
        hist[2 * tid + 1] = excl + a;
        __syncthreads();
#pragma unroll
        for (int k = 0; k < 32; k++) {
            int i = tid + k * 256;
            int r = atomicAdd(&hist[(int)cids[i]], 1);
            g_qsort[(size_t)bt * N1_ + r] =
                make_float4(qp[3 * i], qp[3 * i + 1], qp[3 * i + 2],
                            __int_as_float(i));
        }
    }
}

// ---------------------------------------------------------------------------
// FUSED stages 1+2 (split-3 bf16) — unchanged from R12
// ---------------------------------------------------------------------------
#define HG_SA  0
#define HG_SBF 16384
#define HG_HH  32768
#define HG_HL  65536
#define HG_TOTAL 98304

__global__ __launch_bounds__(256) void k_hgemm_f()
{
    extern __shared__ __align__(128) char smem[];
    const int tid  = threadIdx.x;
    const int wid  = tid >> 5, lane = tid & 31;
    const int z    = blockIdx.z;
    const int nb   = blockIdx.x * 128;
    const int m_w  = (wid & 3) * 32;
    const int n_w  = (wid >> 2) * 64;

    const bf16* A1h = g_wt0h + (z % 3) * CT_ * CIN_;
    const bf16* A1l = g_wt0l + (z % 3) * CT_ * CIN_;
    const bf16* B1h = g_fh + (size_t)(z / 3) * CIN_ * N2_;
    const bf16* B1l = g_fl + (size_t)(z / 3) * CIN_ * N2_;

    const uint32_t sb = smem_u32(smem);
    const int qrow = lane >> 2, qcol = (lane & 3) * 2;

    float d[2][8][4];
#pragma unroll
    for (int mt = 0; mt < 2; mt++)
#pragma unroll
        for (int nt = 0; nt < 8; nt++)
#pragma unroll
            for (int r = 0; r < 4; r++) d[mt][nt][r] = 0.f;

    for (int chunk = 0; chunk < 6; chunk++) {
        const int p  = chunk >> 1;
        const int k0 = (chunk & 1) * 64;
        const bf16* Asrc = (p < 2) ? A1h : A1l;
        const bf16* Bsrc = (p == 1) ? B1l : B1h;
        __syncthreads();
#pragma unroll
        for (int i = 0; i < 4; i++) {
            int idx = tid + i * 256;
            int m = idx >> 3, u = idx & 7;
            uint4 v = *(const uint4*)(Asrc + m * 128 + k0 + u * 8);
            *(uint4*)(smem + HG_SA + m * 128 + ((u * 16) ^ ((m & 7) << 4))) = v;
        }
#pragma unroll
        for (int i = 0; i < 4; i++) {
            int idx = tid + i * 256;
            int kr = idx >> 4, u = idx & 15;
            uint4 v = *(const uint4*)(Bsrc + (size_t)(k0 + kr) * N2_ + nb + u * 8);
            *(uint4*)(smem + HG_SBF + kr * 256 + ((u * 16) ^ ((kr & 7) << 4))) = v;
        }
        __syncthreads();
#pragma unroll
        for (int ks = 0; ks < 4; ks++) {
            uint32_t a[2][4];
#pragma unroll
            for (int mt = 0; mt < 2; mt++) {
                int m = m_w + mt * 16 + (lane & 15);
                uint32_t addr = sb + HG_SA + m * 128 +
                    (((uint32_t)(ks * 32 + (lane >> 4) * 16)) ^ ((m & 7) << 4));
                ldmx4(a[mt], addr);
            }
            uint32_t b[4][4];
#pragma unroll
            for (int pr = 0; pr < 4; pr++) {
                int kr = ks * 16 + (lane & 15);
                uint32_t nc = (uint32_t)(n_w + pr * 16 + (lane >> 4) * 8) * 2;
                uint32_t addr = sb + HG_SBF + kr * 256 + (nc ^ ((kr & 7) << 4));
                ldmx4t(b[pr], addr);
            }
#pragma unroll
            for (int mt = 0; mt < 2; mt++)
#pragma unroll
                for (int nt = 0; nt < 8; nt++)
                    mma_bf16(d[mt][nt], a[mt], &b[nt >> 1][(nt & 1) * 2]);
        }
    }
    __syncthreads();

#pragma unroll
    for (int mt = 0; mt < 2; mt++) {
#pragma unroll
        for (int half = 0; half < 2; half++) {
            int row = m_w + mt * 16 + half * 8 + qrow;
#pragma unroll
            for (int nt = 0; nt < 8; nt++) {
                int col = n_w + nt * 8 + qcol;
                float x = fmaxf(d[mt][nt][half * 2],     0.f);
                float y = fmaxf(d[mt][nt][half * 2 + 1], 0.f);
                bf16 xh, xl, yh, yl;
                split_bf16(x, xh, xl);
                split_bf16(y, yh, yl);
                uint32_t offs = row * 256 + (((uint32_t)(col * 2)) ^ ((row & 7) << 4));
                __nv_bfloat162 vh; vh.x = xh; vh.y = yh;
                __nv_bfloat162 vl; vl.x = xl; vl.y = yl;
                *(__nv_bfloat162*)(smem + HG_HH + offs) = vh;
                *(__nv_bfloat162*)(smem + HG_HL + offs) = vl;
            }
        }
    }

    const bf16* A2h = g_wt1h + (z % 3) * CT_ * CT_;
    const bf16* A2l = g_wt1l + (z % 3) * CT_ * CT_;

    float d2[2][8][4];
#pragma unroll
    for (int mt = 0; mt < 2; mt++)
#pragma unroll
        for (int nt = 0; nt < 8; nt++)
#pragma unroll
            for (int r = 0; r < 4; r++) d2[mt][nt][r] = 0.f;

    for (int chunk = 0; chunk < 6; chunk++) {
        const int p  = chunk >> 1;
        const int k0 = (chunk & 1) * 64;
        const bf16* Asrc = (p < 2) ? A2h : A2l;
        const uint32_t hbase = (p == 1) ? HG_HL : HG_HH;
        __syncthreads();
#pragma unroll
        for (int i = 0; i < 4; i++) {
            int idx = tid + i * 256;
            int m = idx >> 3, u = idx & 7;
            uint4 v = *(const uint4*)(Asrc + m * 128 + k0 + u * 8);
            *(uint4*)(smem + HG_SA + m * 128 + ((u * 16) ^ ((m & 7) << 4))) = v;
        }
        __syncthreads();
#pragma unroll
        for (int ks = 0; ks < 4; ks++) {
            uint32_t a[2][4];
#pragma unroll
            for (int mt = 0; mt < 2; mt++) {
                int m = m_w + mt * 16 + (lane & 15);
                uint32_t addr = sb + HG_SA + m * 128 +
                    (((uint32_t)(ks * 32 + (lane >> 4) * 16)) ^ ((m & 7) << 4));
                ldmx4(a[mt], addr);
            }
            uint32_t b[4][4];
#pragma unroll
            for (int pr = 0; pr < 4; pr++) {
                int kr = ks * 16 + (lane & 15);
                uint32_t nc = (uint32_t)(n_w + pr * 16 + (lane >> 4) * 8) * 2;
                uint32_t addr = sb + hbase + (k0 + kr) * 256 +
                                (nc ^ ((kr & 7) << 4));
                ldmx4t(b[pr], addr);
            }
#pragma unroll
            for (int mt = 0; mt < 2; mt++)
#pragma unroll
                for (int nt = 0; nt < 8; nt++)
                    mma_bf16(d2[mt][nt], a[mt], &b[nt >> 1][(nt & 1) * 2]);
        }
    }

    float* C = g_tt + (size_t)z * N2_ * CT_;
#pragma unroll
    for (int mt = 0; mt < 2; mt++) {
#pragma unroll
        for (int half = 0; half < 2; half++) {
            int row = m_w + mt * 16 + half * 8 + qrow;
#pragma unroll
            for (int nt = 0; nt < 8; nt++) {
                int col = nb + n_w + nt * 8 + qcol;
                C[(size_t)col * CT_ + row]       = fmaxf(d2[mt][nt][half * 2],     0.f);
                C[(size_t)(col + 1) * CT_ + row] = fmaxf(d2[mt][nt][half * 2 + 1], 0.f);
            }
        }
    }
}

// ---------------------------------------------------------------------------
// KNN + interp — unchanged from R11/R12 (WIN config)
// ---------------------------------------------------------------------------
__global__ __launch_bounds__(256) void k_knn_interp()
{
    const int bt  = blockIdx.y;
    const int bq  = bt / 9;
    const int t1  = bt % 9 + 1;
    const int qb  = blockIdx.x * 256;
    const int tid = threadIdx.x;

    int t2s[2], ks[2], nseg = 0;
    if ((t1 & 1) == 0) { t2s[0] = t1 / 2 - 1; ks[0] = 1; nseg = 1; }
    else {
        int p = (t1 - 1) >> 1;
        if (p - 1 >= 0) { t2s[nseg] = p - 1; ks[nseg] = 2; nseg++; }
        if (p <= 3)     { t2s[nseg] = p;     ks[nseg] = 0; nseg++; }
    }

    float4 qv = g_qsort[(size_t)bt * N1_ + qb + tid];
    const float qx = qv.x, qy = qv.y, qz = qv.z;
    const int   qid = __float_as_int(qv.w);
    const float nx = -2.f * qx, ny = -2.f * qy, nz = -2.f * qz;
    const float qq = fmaf(qx, qx, fmaf(qy, qy, qz * qz));

    const int g_home = (qb + (tid & ~31)) >> 7;

    __shared__ float4 ss [2048];
    __shared__ int    ssi[2048];
    __shared__ float4 smeta[128];
    __shared__ float  swt[256 * 3];
    __shared__ int    sof[256 * 3];
    __shared__ int    sqd[256];

    float b0 = 3.4e38f, b1 = 3.4e38f, b2 = 3.4e38f;
    int   o0 = 0, o1 = 0, o2 = 0;

#define EVAL32(blkbase, offbase)                                             \
    _Pragma("unroll 4")                                                      \
    for (int t = 0; t < 32; t++) {                                           \
        float4 v = ss[(blkbase) + t];                                        \
        float dd = fmaf(v.x, nx, fmaf(v.y, ny, fmaf(v.z, nz, v.w)));         \
        if (dd < b2) {                                                       \
            int off = (offbase) + (ssi[(blkbase) + t] << 7);                 \
            if (dd < b1) {                                                   \
                b2 = b1; o2 = o1;                                            \
                if (dd < b0) { b1 = b0; o1 = o0; b0 = dd; o0 = off; }        \
                else         { b1 = dd; o1 = off; }                          \
            } else { b2 = dd; o2 = off; }                                    \
        }                                                                    \
    }

    for (int s = 0; s < nseg; s++) {
        const int set = bq * 4 + t2s[s];
        const float4* S  = g_ssort + set * N2_;
        const int*    SI = g_sidx  + set * N2_;
        const int offbase = (set * 3 + ks[s]) * (N2_ * CT_);
        __syncthreads();
#pragma unroll
        for (int i = 0; i < 8; i++) {
            int t = tid + i * 256;
            ss[t]  = S[t];
            ssi[t] = SI[t];
        }
        if (tid < 128) smeta[tid] = g_gmeta[set * 128 + tid];
        __syncthreads();
        EVAL32(g_home * 32, offbase);
        for (int j = 1; j < 64; j++) {
            int off_g = (j + 1) >> 1;
            int g = ((j & 1) ? (g_home + off_g) : (g_home - off_g)) & 63;
            float4 lo = smeta[2 * g];
            float4 hi = smeta[2 * g + 1];
            float ddx = fmaxf(fmaxf(lo.x - qx, qx - hi.x), 0.f);
            float ddy = fmaxf(fmaxf(lo.y - qy, qy - hi.y), 0.f);
            float ddz = fmaxf(fmaxf(lo.z - qz, qz - hi.z), 0.f);
            float lb2 = fmaf(ddx, ddx, fmaf(ddy, ddy, ddz * ddz));
            float thr = (b2 + qq) * 1.0001f + 1e-5f;
            if (__all_sync(0xFFFFFFFFu, lb2 > thr)) continue;
            EVAL32(g * 32, offbase);
        }
    }

    {
        float w0 = 1.f / (b0 + qq + 1e-8f);
        float w1 = 1.f / (b1 + qq + 1e-8f);
        float w2 = 1.f / (b2 + qq + 1e-8f);
        float si = 1.f / (w0 + w1 + w2);
        swt[tid * 3]     = w0 * si;
        swt[tid * 3 + 1] = w1 * si;
        swt[tid * 3 + 2] = w2 * si;
        sof[tid * 3]     = o0;
        sof[tid * 3 + 1] = o1;
        sof[tid * 3 + 2] = o2;
        sqd[tid]         = qid;
    }
    __syncthreads();

    const int sub = tid >> 7;
    const int c   = tid & 127;
#pragma unroll 4
    for (int it = 0; it < 128; it++) {
        int ql = it + sub * 128;
        float w0 = swt[ql * 3], w1 = swt[ql * 3 + 1], w2 = swt[ql * 3 + 2];
        int   p0 = sof[ql * 3], p1 = sof[ql * 3 + 1], p2 = sof[ql * 3 + 2];
        float v = w0 * g_tt[p0 + c] + w1 * g_tt[p1 + c] + w2 * g_tt[p2 + c];
        bf16 hi, lo;
        split_bf16(v, hi, lo);
        size_t dd = ((size_t)bt * N1_ + sqd[ql]) * KD3_ + c;
        g_bhi[dd] = hi;
        g_blo[dd] = lo;
    }
}

// ---------------------------------------------------------------------------
// Stage 3 via mma.sync bf16 split-3 — k0-group operand reuse + group-level
// double buffering. Per 96KB stage: AH 32K | AL 32K | BH 16K | BL 16K.
// Two stages = 192KB dynamic smem (1 CTA/SM). Per k0 group one cp.async
// commit of all 4 operands; three passes t0=(AH,BH), t1=(AH,BL), t2=(AL,BH).
// ---------------------------------------------------------------------------
#define M3_STG   98304
#define M3_AH    0
#define M3_AL    32768
#define M3_BH    65536
#define M3_BL    81920
#define M3_TOTAL (2 * M3_STG)

__global__ __launch_bounds__(512, 1) void k_mma3(
    const float* __restrict__ gamma, const float* __restrict__ beta,
    const float* __restrict__ mean,  const float* __restrict__ var,
    float* __restrict__ out)
{
    extern __shared__ __align__(128) char smem[];
    const int tid  = threadIdx.x;
    const int wid  = tid >> 5, lane = tid & 31;
    const int bt   = blockIdx.z;
    const int nb   = blockIdx.x * 128;
    const int m_w  = (wid & 7) * 32;
    const int n_w  = (wid >> 3) * 64;

    const uint32_t sb = smem_u32(smem);
    const size_t   brow = ((size_t)bt * N1_ + nb) * KD3_;

    float d[2][8][4];
#pragma unroll
    for (int mt = 0; mt < 2; mt++)
#pragma unroll
        for (int nt = 0; nt < 8; nt++)
#pragma unroll
            for (int r = 0; r < 4; r++) d[mt][nt][r] = 0.f;

    // async load of k0-group g (96KB: AH, AL, BH, BL) into stage s; 1 commit
#define M3_LOADG(g, s) {                                                     \
        const int k0_ = (g) * 64;                                            \
        const uint32_t base = sb + (s) * M3_STG;                             \
        _Pragma("unroll")                                                    \
        for (int i = 0; i < 4; i++) {                                        \
            int idx = tid + i * 512;                                         \
            int m = idx >> 3, u = idx & 7;                                   \
            uint32_t so = m * 128 + ((u * 16) ^ ((m & 7) << 4));             \
            cpa16(base + M3_AH + so, g_whi + m * KD3_ + k0_ + u * 8);        \
            cpa16(base + M3_AL + so, g_wlo + m * KD3_ + k0_ + u * 8);        \
        }                                                                    \
        _Pragma("unroll")                                                    \
        for (int i = 0; i < 2; i++) {                                        \
            int idx = tid + i * 512;                                         \
            int n = idx >> 3, u = idx & 7;                                   \
            uint32_t so = n * 128 + ((u * 16) ^ ((n & 7) << 4));             \
            const bf16* bh = g_bhi + brow + (size_t)n * KD3_ + k0_ + u * 8;  \
            const bf16* bl = g_blo + brow + (size_t)n * KD3_ + k0_ + u * 8;  \
            cpa16(base + M3_BH + so, bh);                                    \
            cpa16(base + M3_BL + so, bl);                                    \
        }                                                                    \
        CPA_COMMIT();                                                        \
    }

    M3_LOADG(0, 0);
    M3_LOADG(1, 1);

    for (int g = 0; g < 3; g++) {
        if (g < 2) CPA_WAIT(1); else CPA_WAIT(0);
        __syncthreads();
        const uint32_t base = sb + (g & 1) * M3_STG;
#pragma unroll
        for (int t = 0; t < 3; t++) {
            const uint32_t abase = base + ((t < 2) ? M3_AH : M3_AL);
            const uint32_t bbase = base + ((t == 1) ? M3_BL : M3_BH);
#pragma unroll
            for (int ksi = 0; ksi < 4; ksi++) {
                uint32_t a[2][4];
#pragma unroll
                for (int mt = 0; mt < 2; mt++) {
                    int m = m_w + mt * 16 + (lane & 15);
                    uint32_t addr = abase + m * 128 +
                        (((uint32_t)(ksi * 32 + (lane >> 4) * 16)) ^ ((m & 7) << 4));
                    ldmx4(a[mt], addr);
                }
                uint32_t b[4][4];
#pragma unroll
                for (int pr = 0; pr < 4; pr++) {
                    int n = n_w + pr * 16 + (lane >> 4) * 8 + (lane & 7);
                    uint32_t addr = bbase + n * 128 +
                        (((uint32_t)(ksi * 32 + ((lane >> 3) & 1) * 16)) ^ ((n & 7) << 4));
                    ldmx4(b[pr], addr);
                }
#pragma unroll
                for (int mt = 0; mt < 2; mt++)
#pragma unroll
                    for (int nt = 0; nt < 8; nt++)
                        mma_bf16(d[mt][nt], a[mt], &b[nt >> 1][(nt & 1) * 2]);
            }
        }
        __syncthreads();
        if (g == 0) M3_LOADG(2, 0);
    }

    const int qrow = lane >> 2, qcol = (lane & 3) * 2;
#pragma unroll
    for (int mt = 0; mt < 2; mt++) {
#pragma unroll
        for (int half = 0; half < 2; half++) {
            int m = m_w + mt * 16 + half * 8 + qrow;
            float sc = gamma[m] * rsqrtf(var[m] + 1e-5f);
            float bi = beta[m] - mean[m] * sc;
            float* Cp = out + ((size_t)bt * CS_ + m) * N1_ + nb + n_w;
#pragma unroll
            for (int nt = 0; nt < 8; nt++) {
                float x = fmaxf(d[mt][nt][half * 2]     * sc + bi, 0.f);
                float y = fmaxf(d[mt][nt][half * 2 + 1] * sc + bi, 0.f);
                *(float2*)&Cp[nt * 8 + qcol] = make_float2(x, y);
            }
        }
    }
}

// ---------------------------------------------------------------------------
extern "C" void kernel_launch(void* const* d_in, const int* in_sizes, int n_in,
                              void* d_out, int out_size)
{
    const float* xyzs   = (const float*)d_in[0];
    const float* oxyzs  = (const float*)d_in[1];
    const float* feats  = (const float*)d_in[2];
    const float* ofeats = (const float*)d_in[3];
    const float* Wt0    = (const float*)d_in[4];
    const float* Wt1    = (const float*)d_in[5];
    const float* Ws     = (const float*)d_in[6];
    const float* gamma  = (const float*)d_in[7];
    const float* beta   = (const float*)d_in[8];
    const float* mean   = (const float*)d_in[9];
    const float* var    = (const float*)d_in[10];

    const int NEWF = B_ * L1_ * CS_ * N1_;
    int ofs = out_size - NEWF;
    float* outF = (float*)d_out;
    if (ofs > 0) {
        cudaMemcpyAsync(d_out, d_in[1], (size_t)ofs * sizeof(float),
                        cudaMemcpyDeviceToDevice, 0);
        outF += ofs;
    }

    cudaFuncSetAttribute(k_hgemm_f, cudaFuncAttributeMaxDynamicSharedMemorySize,
                         HG_TOTAL);
    cudaFuncSetAttribute(k_mma3, cudaFuncAttributeMaxDynamicSharedMemorySize,
                         M3_TOTAL);

    k_prep<<<PREP_W + PREP_F + PREP_OF + PREP_SS + PREP_SQ, 256>>>(
        Wt0, Wt1, Ws, feats, ofeats, xyzs, oxyzs);            // kernel 1
    k_hgemm_f<<<dim3(16, 1, 24), 256, HG_TOTAL>>>();          // kernel 2
    k_knn_interp<<<dim3(32, 18), 256>>>();                    // kernel 3
    k_mma3<<<dim3(64, 1, 18), 512, M3_TOTAL>>>(gamma, beta, mean, var, outF);
}

// round 14
// speedup vs baseline: 1.1058x; 1.1058x over previous
#include <cuda_runtime.h>
#include <cuda_bf16.h>
#include <cstdint>

// Problem constants
#define B_     2
#define L2_    4
#define N2_    2048
#define L1_    9
#define N1_    8192
#define CIN_   128
#define CT_    128
#define CS_    256
#define CORIG_ 64
#define KD3_   192   // CT_ + CORIG_

typedef __nv_bfloat16 bf16;

// Scratch (static device globals — no runtime allocation)
__device__ float g_tt [B_*L2_*3*N2_*CT_];                 // stage-2 out, n-major [z][n][o] fp32
__device__ __align__(128) float4 g_ssort[8*N2_];          // cell-sorted seeds (x,y,z,|s|^2)
__device__ __align__(128) int    g_sidx [8*N2_];          // original seed index per sorted slot
__device__ __align__(128) float4 g_gmeta[8*64*2];         // per-32-seed-block AABB lo/hi
__device__ __align__(128) float4 g_qsort[18*N1_];         // cell-sorted queries (x,y,z,qid)
__device__ __align__(128) bf16 g_wt0h[3*CT_*CIN_];
__device__ __align__(128) bf16 g_wt0l[3*CT_*CIN_];
__device__ __align__(128) bf16 g_wt1h[3*CT_*CT_];
__device__ __align__(128) bf16 g_wt1l[3*CT_*CT_];
__device__ __align__(128) bf16 g_whi [CS_*KD3_];
__device__ __align__(128) bf16 g_wlo [CS_*KD3_];
__device__ __align__(128) bf16 g_fh  [(size_t)B_*L2_*CIN_*N2_];
__device__ __align__(128) bf16 g_fl  [(size_t)B_*L2_*CIN_*N2_];
__device__ __align__(128) bf16 g_bhi [(size_t)B_*L1_*N1_*KD3_];
__device__ __align__(128) bf16 g_blo [(size_t)B_*L1_*N1_*KD3_];

__device__ __forceinline__ uint32_t smem_u32(const void* p) {
    uint32_t a;
    asm("{ .reg .u64 t; cvta.to.shared.u64 t, %1; cvt.u32.u64 %0, t; }"
        : "=r"(a) : "l"(p));
    return a;
}
__device__ __forceinline__ void ldmx4(uint32_t* r, uint32_t addr) {
    asm volatile("ldmatrix.sync.aligned.m8n8.x4.shared.b16 {%0,%1,%2,%3}, [%4];"
                 : "=r"(r[0]), "=r"(r[1]), "=r"(r[2]), "=r"(r[3]) : "r"(addr));
}
__device__ __forceinline__ void ldmx4t(uint32_t* r, uint32_t addr) {
    asm volatile("ldmatrix.sync.aligned.m8n8.x4.trans.shared.b16 {%0,%1,%2,%3}, [%4];"
                 : "=r"(r[0]), "=r"(r[1]), "=r"(r[2]), "=r"(r[3]) : "r"(addr));
}
__device__ __forceinline__ void mma_bf16(float* d, const uint32_t* a,
                                         const uint32_t* b) {
    asm volatile("mma.sync.aligned.m16n8k16.row.col.f32.bf16.bf16.f32 "
                 "{%0,%1,%2,%3}, {%4,%5,%6,%7}, {%8,%9}, {%0,%1,%2,%3};"
                 : "+f"(d[0]), "+f"(d[1]), "+f"(d[2]), "+f"(d[3])
                 : "r"(a[0]), "r"(a[1]), "r"(a[2]), "r"(a[3]),
                   "r"(b[0]), "r"(b[1]));
}
__device__ __forceinline__ void split_bf16(float v, bf16& hi, bf16& lo) {
    hi = __float2bfloat16(v);
    lo = __float2bfloat16(v - __bfloat162float(hi));
}
__device__ __forceinline__ void cpa16(uint32_t saddr, const void* g) {
    asm volatile("cp.async.cg.shared.global [%0], [%1], 16;"
                 :: "r"(saddr), "l"(g));
}
#define CPA_COMMIT() asm volatile("cp.async.commit_group;" ::: "memory")
#define CPA_WAIT(n)  asm volatile("cp.async.wait_group %0;" :: "n"(n) : "memory")

__device__ __forceinline__ int mpart(int v) {      // 3-bit spread to bits 0,3,6
    return (v & 1) | ((v & 2) << 2) | ((v & 4) << 4);
}
__device__ __forceinline__ int cell_id(float x, float y, float z) {
    int cx = min(7, max(0, (int)floorf(x) + 4));
    int cy = min(7, max(0, (int)floorf(y) + 4));
    int cz = min(7, max(0, (int)floorf(z) + 4));
    return (mpart(cx) << 2) | (mpart(cy) << 1) | mpart(cz);
}

// ---------------------------------------------------------------------------
// Prep: weight/feature/OF splits + seed sort (+AABBs) + query sort
// ---------------------------------------------------------------------------
#define PREP_W   576
#define PREP_F   8192
#define PREP_OF  2304
#define PREP_SS  8
#define PREP_SQ  18
__global__ __launch_bounds__(256) void k_prep(
    const float* __restrict__ Wt0, const float* __restrict__ Wt1,
    const float* __restrict__ Ws,  const float* __restrict__ F,
    const float* __restrict__ OF,  const float* __restrict__ xyzs,
    const float* __restrict__ oxyzs)
{
    __shared__ __align__(16) char sbuf[20992];
    const int bx  = blockIdx.x;
    const int tid = threadIdx.x;
    if (bx < PREP_W) {
        int i = bx * 256 + tid;
        bf16 hi, lo;
        if (i < 49152) {
            split_bf16(Wt0[i], hi, lo);
            g_wt0h[i] = hi; g_wt0l[i] = lo;
        } else if (i < 98304) {
            int j = i - 49152;
            split_bf16(Wt1[j], hi, lo);
            g_wt1h[j] = hi; g_wt1l[j] = lo;
        } else {
            int j = i - 98304;
            split_bf16(Ws[j], hi, lo);
            g_whi[j] = hi; g_wlo[j] = lo;
        }
    } else if (bx < PREP_W + PREP_F) {
        size_t i = (size_t)(bx - PREP_W) * 256 + tid;
        bf16 hi, lo;
        split_bf16(F[i], hi, lo);
        g_fh[i] = hi; g_fl[i] = lo;
    } else if (bx < PREP_W + PREP_F + PREP_OF) {
        const int rb = bx - PREP_W - PREP_F;
        const int bt = rb >> 7;
        const int nb = (rb & 127) * 64;
        bf16 (*sh)[65] = (bf16(*)[65])sbuf;
        bf16 (*sl)[65] = (bf16(*)[65])(sbuf + 64 * 65 * 2);
#pragma unroll
        for (int i = 0; i < 16; i++) {
            int idx = tid + i * 256;
            int c = idx >> 6, n = idx & 63;
            bf16 hi, lo;
            split_bf16(OF[((size_t)bt * CORIG_ + c) * N1_ + nb + n], hi, lo);
            sh[c][n] = hi; sl[c][n] = lo;
        }
        __syncthreads();
#pragma unroll
        for (int i = 0; i < 16; i++) {
            int idx = tid + i * 256;
            int n = idx >> 6, c = idx & 63;
            size_t d = ((size_t)bt * N1_ + nb + n) * KD3_ + CT_ + c;
            g_bhi[d] = sh[c][n];
            g_blo[d] = sl[c][n];
        }
    } else if (bx < PREP_W + PREP_F + PREP_OF + PREP_SS) {
        // ---- seed counting sort by Morton cell + per-block AABBs ----
        const int set = bx - PREP_W - PREP_F - PREP_OF;   // 0..7 = bq*4+t2
        int* cids = (int*)sbuf;              // 2048
        int* hist = (int*)(sbuf + 8192);     // 512
        int* part = (int*)(sbuf + 10240);    // 256
        const float* sp = xyzs + (size_t)set * N2_ * 3;
        hist[tid] = 0; hist[tid + 256] = 0;
        __syncthreads();
#pragma unroll
        for (int k = 0; k < 8; k++) {
            int i = tid + k * 256;
            int cid = cell_id(sp[3 * i], sp[3 * i + 1], sp[3 * i + 2]);
            cids[i] = cid;
            atomicAdd(&hist[cid], 1);
        }
        __syncthreads();
        int a = hist[2 * tid], b = hist[2 * tid + 1];
        int s = a + b;
        part[tid] = s;
        __syncthreads();
        for (int off = 1; off < 256; off <<= 1) {
            int v = (tid >= off) ? part[tid - off] : 0;
            __syncthreads();
            part[tid] += v;
            __syncthreads();
        }
        int excl = part[tid] - s;
        hist[2 * tid]     = excl;
        hist[2 * tid + 1] = excl + a;
        __syncthreads();
#pragma unroll
        for (int k = 0; k < 8; k++) {
            int i = tid + k * 256;
            int r = atomicAdd(&hist[cids[i]], 1);
            float x = sp[3 * i], y = sp[3 * i + 1], z = sp[3 * i + 2];
            g_ssort[set * N2_ + r] =
                make_float4(x, y, z, x * x + y * y + z * z);
            g_sidx[set * N2_ + r] = i;
        }
        __syncthreads();
        if (tid < 64) {
            float lx = 3.4e38f, ly = 3.4e38f, lz = 3.4e38f;
            float hx = -3.4e38f, hy = -3.4e38f, hz = -3.4e38f;
#pragma unroll 4
            for (int t = 0; t < 32; t++) {
                float4 v = g_ssort[set * N2_ + tid * 32 + t];
                lx = fminf(lx, v.x); hx = fmaxf(hx, v.x);
                ly = fminf(ly, v.y); hy = fmaxf(hy, v.y);
                lz = fminf(lz, v.z); hz = fmaxf(hz, v.z);
            }
            g_gmeta[(set * 64 + tid) * 2]     = make_float4(lx, ly, lz, 0.f);
            g_gmeta[(set * 64 + tid) * 2 + 1] = make_float4(hx, hy, hz, 0.f);
        }
    } else {
        // ---- query counting sort by Morton cell ----
        const int bt = bx - PREP_W - PREP_F - PREP_OF - PREP_SS;  // 0..17
        short* cids = (short*)sbuf;          // 8192
        int*   hist = (int*)(sbuf + 16384);  // 512
        int*   part = (int*)(sbuf + 18432);  // 256
        const float* qp = oxyzs + (size_t)bt * N1_ * 3;
        hist[tid] = 0; hist[tid + 256] = 0;
        __syncthreads();
#pragma unroll
        for (int k = 0; k < 32; k++) {
            int i = tid + k * 256;
            int cid = cell_id(qp[3 * i], qp[3 * i + 1], qp[3 * i + 2]);
            cids[i] = (short)cid;
            atomicAdd(&hist[cid], 1);
        }
        __syncthreads();
        int a = hist[2 * tid], b = hist[2 * tid + 1];
        int s = a + b;
        part[tid] = s;
        __syncthreads();
        for (int off = 1; off < 256; off <<= 1) {
            int v = (tid >= off) ? part[tid - off] : 0;
            __syncthreads();
            part[tid] += v;
            __syncthreads();
        }
        int excl = part[tid] - s;
        hist[2 * tid]     = excl;
        hist[2 * tid + 1] = excl + a;
        __syncthreads();
#pragma unroll
        for (int k = 0; k < 32; k++) {
            int i = tid + k * 256;
            int r = atomicAdd(&hist[(int)cids[i]], 1);
            g_qsort[(size_t)bt * N1_ + r] =
                make_float4(qp[3 * i], qp[3 * i + 1], qp[3 * i + 2],
                            __int_as_float(i));
        }
    }
}

// ---------------------------------------------------------------------------
// FUSED stages 1+2 (split-3 bf16) — unchanged from R12
// ---------------------------------------------------------------------------
#define HG_SA  0
#define HG_SBF 16384
#define HG_HH  32768
#define HG_HL  65536
#define HG_TOTAL 98304

__global__ __launch_bounds__(256) void k_hgemm_f()
{
    extern __shared__ __align__(128) char smem[];
    const int tid  = threadIdx.x;
    const int wid  = tid >> 5, lane = tid & 31;
    const int z    = blockIdx.z;
    const int nb   = blockIdx.x * 128;
    const int m_w  = (wid & 3) * 32;
    const int n_w  = (wid >> 2) * 64;

    const bf16* A1h = g_wt0h + (z % 3) * CT_ * CIN_;
    const bf16* A1l = g_wt0l + (z % 3) * CT_ * CIN_;
    const bf16* B1h = g_fh + (size_t)(z / 3) * CIN_ * N2_;
    const bf16* B1l = g_fl + (size_t)(z / 3) * CIN_ * N2_;

    const uint32_t sb = smem_u32(smem);
    const int qrow = lane >> 2, qcol = (lane & 3) * 2;

    float d[2][8][4];
#pragma unroll
    for (int mt = 0; mt < 2; mt++)
#pragma unroll
        for (int nt = 0; nt < 8; nt++)
#pragma unroll
            for (int r = 0; r < 4; r++) d[mt][nt][r] = 0.f;

    for (int chunk = 0; chunk < 6; chunk++) {
        const int p  = chunk >> 1;
        const int k0 = (chunk & 1) * 64;
        const bf16* Asrc = (p < 2) ? A1h : A1l;
        const bf16* Bsrc = (p == 1) ? B1l : B1h;
        __syncthreads();
#pragma unroll
        for (int i = 0; i < 4; i++) {
            int idx = tid + i * 256;
            int m = idx >> 3, u = idx & 7;
            uint4 v = *(const uint4*)(Asrc + m * 128 + k0 + u * 8);
            *(uint4*)(smem + HG_SA + m * 128 + ((u * 16) ^ ((m & 7) << 4))) = v;
        }
#pragma unroll
        for (int i = 0; i < 4; i++) {
            int idx = tid + i * 256;
            int kr = idx >> 4, u = idx & 15;
            uint4 v = *(const uint4*)(Bsrc + (size_t)(k0 + kr) * N2_ + nb + u * 8);
            *(uint4*)(smem + HG_SBF + kr * 256 + ((u * 16) ^ ((kr & 7) << 4))) = v;
        }
        __syncthreads();
#pragma unroll
        for (int ks = 0; ks < 4; ks++) {
            uint32_t a[2][4];
#pragma unroll
            for (int mt = 0; mt < 2; mt++) {
                int m = m_w + mt * 16 + (lane & 15);
                uint32_t addr = sb + HG_SA + m * 128 +
                    (((uint32_t)(ks * 32 + (lane >> 4) * 16)) ^ ((m & 7) << 4));
                ldmx4(a[mt], addr);
            }
            uint32_t b[4][4];
#pragma unroll
            for (int pr = 0; pr < 4; pr++) {
                int kr = ks * 16 + (lane & 15);
                uint32_t nc = (uint32_t)(n_w + pr * 16 + (lane >> 4) * 8) * 2;
                uint32_t addr = sb + HG_SBF + kr * 256 + (nc ^ ((kr & 7) << 4));
                ldmx4t(b[pr], addr);
            }
#pragma unroll
            for (int mt = 0; mt < 2; mt++)
#pragma unroll
                for (int nt = 0; nt < 8; nt++)
                    mma_bf16(d[mt][nt], a[mt], &b[nt >> 1][(nt & 1) * 2]);
        }
    }
    __syncthreads();

#pragma unroll
    for (int mt = 0; mt < 2; mt++) {
#pragma unroll
        for (int half = 0; half < 2; half++) {
            int row = m_w + mt * 16 + half * 8 + qrow;
#pragma unroll
            for (int nt = 0; nt < 8; nt++) {
                int col = n_w + nt * 8 + qcol;
                float x = fmaxf(d[mt][nt][half * 2],     0.f);
                float y = fmaxf(d[mt][nt][half * 2 + 1], 0.f);
                bf16 xh, xl, yh, yl;
                split_bf16(x, xh, xl);
                split_bf16(y, yh, yl);
                uint32_t offs = row * 256 + (((uint32_t)(col * 2)) ^ ((row & 7) << 4));
                __nv_bfloat162 vh; vh.x = xh; vh.y = yh;
                __nv_bfloat162 vl; vl.x = xl; vl.y = yl;
                *(__nv_bfloat162*)(smem + HG_HH + offs) = vh;
                *(__nv_bfloat162*)(smem + HG_HL + offs) = vl;
            }
        }
    }

    const bf16* A2h = g_wt1h + (z % 3) * CT_ * CT_;
    const bf16* A2l = g_wt1l + (z % 3) * CT_ * CT_;

    float d2[2][8][4];
#pragma unroll
    for (int mt = 0; mt < 2; mt++)
#pragma unroll
        for (int nt = 0; nt < 8; nt++)
#pragma unroll
            for (int r = 0; r < 4; r++) d2[mt][nt][r] = 0.f;

    for (int chunk = 0; chunk < 6; chunk++) {
        const int p  = chunk >> 1;
        const int k0 = (chunk & 1) * 64;
        const bf16* Asrc = (p < 2) ? A2h : A2l;
        const uint32_t hbase = (p == 1) ? HG_HL : HG_HH;
        __syncthreads();
#pragma unroll
        for (int i = 0; i < 4; i++) {
            int idx = tid + i * 256;
            int m = idx >> 3, u = idx & 7;
            uint4 v = *(const uint4*)(Asrc + m * 128 + k0 + u * 8);
            *(uint4*)(smem + HG_SA + m * 128 + ((u * 16) ^ ((m & 7) << 4))) = v;
        }
        __syncthreads();
#pragma unroll
        for (int ks = 0; ks < 4; ks++) {
            uint32_t a[2][4];
#pragma unroll
            for (int mt = 0; mt < 2; mt++) {
                int m = m_w + mt * 16 + (lane & 15);
                uint32_t addr = sb + HG_SA + m * 128 +
                    (((uint32_t)(ks * 32 + (lane >> 4) * 16)) ^ ((m & 7) << 4));
                ldmx4(a[mt], addr);
            }
            uint32_t b[4][4];
#pragma unroll
            for (int pr = 0; pr < 4; pr++) {
                int kr = ks * 16 + (lane & 15);
                uint32_t nc = (uint32_t)(n_w + pr * 16 + (lane >> 4) * 8) * 2;
                uint32_t addr = sb + hbase + (k0 + kr) * 256 +
                                (nc ^ ((kr & 7) << 4));
                ldmx4t(b[pr], addr);
            }
#pragma unroll
            for (int mt = 0; mt < 2; mt++)
#pragma unroll
                for (int nt = 0; nt < 8; nt++)
                    mma_bf16(d2[mt][nt], a[mt], &b[nt >> 1][(nt & 1) * 2]);
        }
    }

    float* C = g_tt + (size_t)z * N2_ * CT_;
#pragma unroll
    for (int mt = 0; mt < 2; mt++) {
#pragma unroll
        for (int half = 0; half < 2; half++) {
            int row = m_w + mt * 16 + half * 8 + qrow;
#pragma unroll
            for (int nt = 0; nt < 8; nt++) {
                int col = nb + n_w + nt * 8 + qcol;
                C[(size_t)col * CT_ + row]       = fmaxf(d2[mt][nt][half * 2],     0.f);
                C[(size_t)(col + 1) * CT_ + row] = fmaxf(d2[mt][nt][half * 2 + 1], 0.f);
            }
        }
    }
}

// ---------------------------------------------------------------------------
// KNN + interp — unchanged (WIN config)
// ---------------------------------------------------------------------------
__global__ __launch_bounds__(256) void k_knn_interp()
{
    const int bt  = blockIdx.y;
    const int bq  = bt / 9;
    const int t1  = bt % 9 + 1;
    const int qb  = blockIdx.x * 256;
    const int tid = threadIdx.x;

    int t2s[2], ks[2], nseg = 0;
    if ((t1 & 1) == 0) { t2s[0] = t1 / 2 - 1; ks[0] = 1; nseg = 1; }
    else {
        int p = (t1 - 1) >> 1;
        if (p - 1 >= 0) { t2s[nseg] = p - 1; ks[nseg] = 2; nseg++; }
        if (p <= 3)     { t2s[nseg] = p;     ks[nseg] = 0; nseg++; }
    }

    float4 qv = g_qsort[(size_t)bt * N1_ + qb + tid];
    const float qx = qv.x, qy = qv.y, qz = qv.z;
    const int   qid = __float_as_int(qv.w);
    const float nx = -2.f * qx, ny = -2.f * qy, nz = -2.f * qz;
    const float qq = fmaf(qx, qx, fmaf(qy, qy, qz * qz));

    const int g_home = (qb + (tid & ~31)) >> 7;

    __shared__ float4 ss [2048];
    __shared__ int    ssi[2048];
    __shared__ float4 smeta[128];
    __shared__ float  swt[256 * 3];
    __shared__ int    sof[256 * 3];
    __shared__ int    sqd[256];

    float b0 = 3.4e38f, b1 = 3.4e38f, b2 = 3.4e38f;
    int   o0 = 0, o1 = 0, o2 = 0;

#define EVAL32(blkbase, offbase)                                             \
    _Pragma("unroll 4")                                                      \
    for (int t = 0; t < 32; t++) {                                           \
        float4 v = ss[(blkbase) + t];                                        \
        float dd = fmaf(v.x, nx, fmaf(v.y, ny, fmaf(v.z, nz, v.w)));         \
        if (dd < b2) {                                                       \
            int off = (offbase) + (ssi[(blkbase) + t] << 7);                 \
            if (dd < b1) {                                                   \
                b2 = b1; o2 = o1;                                            \
                if (dd < b0) { b1 = b0; o1 = o0; b0 = dd; o0 = off; }        \
                else         { b1 = dd; o1 = off; }                          \
            } else { b2 = dd; o2 = off; }                                    \
        }                                                                    \
    }

    for (int s = 0; s < nseg; s++) {
        const int set = bq * 4 + t2s[s];
        const float4* S  = g_ssort + set * N2_;
        const int*    SI = g_sidx  + set * N2_;
        const int offbase = (set * 3 + ks[s]) * (N2_ * CT_);
        __syncthreads();
#pragma unroll
        for (int i = 0; i < 8; i++) {
            int t = tid + i * 256;
            ss[t]  = S[t];
            ssi[t] = SI[t];
        }
        if (tid < 128) smeta[tid] = g_gmeta[set * 128 + tid];
        __syncthreads();
        EVAL32(g_home * 32, offbase);
        for (int j = 1; j < 64; j++) {
            int off_g = (j + 1) >> 1;
            int g = ((j & 1) ? (g_home + off_g) : (g_home - off_g)) & 63;
            float4 lo = smeta[2 * g];
            float4 hi = smeta[2 * g + 1];
            float ddx = fmaxf(fmaxf(lo.x - qx, qx - hi.x), 0.f);
            float ddy = fmaxf(fmaxf(lo.y - qy, qy - hi.y), 0.f);
            float ddz = fmaxf(fmaxf(lo.z - qz, qz - hi.z), 0.f);
            float lb2 = fmaf(ddx, ddx, fmaf(ddy, ddy, ddz * ddz));
            float thr = (b2 + qq) * 1.0001f + 1e-5f;
            if (__all_sync(0xFFFFFFFFu, lb2 > thr)) continue;
            EVAL32(g * 32, offbase);
        }
    }

    {
        float w0 = 1.f / (b0 + qq + 1e-8f);
        float w1 = 1.f / (b1 + qq + 1e-8f);
        float w2 = 1.f / (b2 + qq + 1e-8f);
        float si = 1.f / (w0 + w1 + w2);
        swt[tid * 3]     = w0 * si;
        swt[tid * 3 + 1] = w1 * si;
        swt[tid * 3 + 2] = w2 * si;
        sof[tid * 3]     = o0;
        sof[tid * 3 + 1] = o1;
        sof[tid * 3 + 2] = o2;
        sqd[tid]         = qid;
    }
    __syncthreads();

    const int sub = tid >> 7;
    const int c   = tid & 127;
#pragma unroll 4
    for (int it = 0; it < 128; it++) {
        int ql = it + sub * 128;
        float w0 = swt[ql * 3], w1 = swt[ql * 3 + 1], w2 = swt[ql * 3 + 2];
        int   p0 = sof[ql * 3], p1 = sof[ql * 3 + 1], p2 = sof[ql * 3 + 2];
        float v = w0 * g_tt[p0 + c] + w1 * g_tt[p1 + c] + w2 * g_tt[p2 + c];
        bf16 hi, lo;
        split_bf16(v, hi, lo);
        size_t dd = ((size_t)bt * N1_ + sqd[ql]) * KD3_ + c;
        g_bhi[dd] = hi;
        g_blo[dd] = lo;
    }
}

// ---------------------------------------------------------------------------
// Stage 3 via mma.sync bf16 split-3 — R12 pipeline, 256-thread CTA,
// M=128 x N=128 tile, 2 CTAs/SM (regs capped via launch_bounds(256,2)).
// Per stage: A 16KB | B 16KB; two stages = 64KB dynamic smem.
// ---------------------------------------------------------------------------
#define M3_STG   32768
#define M3_SA    0
#define M3_SB    16384
#define M3_TOTAL (2 * M3_STG)

__global__ __launch_bounds__(256, 2) void k_mma3(
    const float* __restrict__ gamma, const float* __restrict__ beta,
    const float* __restrict__ mean,  const float* __restrict__ var,
    float* __restrict__ out)
{
    extern __shared__ __align__(128) char smem[];
    const int tid  = threadIdx.x;
    const int wid  = tid >> 5, lane = tid & 31;
    const int bt   = blockIdx.z;
    const int m0   = blockIdx.y * 128;
    const int nb   = blockIdx.x * 128;
    const int m_w  = (wid & 3) * 32;
    const int n_w  = (wid >> 2) * 64;

    const uint32_t sb = smem_u32(smem);
    const size_t   brow = ((size_t)bt * N1_ + nb) * KD3_;

    float d[2][8][4];
#pragma unroll
    for (int mt = 0; mt < 2; mt++)
#pragma unroll
        for (int nt = 0; nt < 8; nt++)
#pragma unroll
            for (int r = 0; r < 4; r++) d[mt][nt][r] = 0.f;

    // async load of chunk c into stage s (A 16KB + B 16KB, one commit)
#define M3_LOAD(c, s) {                                                      \
        const int t_  = (c) % 3;                                             \
        const int k0_ = ((c) / 3) * 64;                                      \
        const bf16* Asrc = ((t_ < 2) ? g_whi : g_wlo) + (size_t)m0 * KD3_;   \
        const bf16* Bsrc = (t_ == 1) ? g_blo : g_bhi;                        \
        const uint32_t base = sb + (s) * M3_STG;                             \
        _Pragma("unroll")                                                    \
        for (int i = 0; i < 4; i++) {                                        \
            int idx = tid + i * 256;                                         \
            int m = idx >> 3, u = idx & 7;                                   \
            cpa16(base + M3_SA + m * 128 + ((u * 16) ^ ((m & 7) << 4)),      \
                  Asrc + m * KD3_ + k0_ + u * 8);                            \
        }                                                                    \
        _Pragma("unroll")                                                    \
        for (int i = 0; i < 4; i++) {                                        \
            int idx = tid + i * 256;                                         \
            int n = idx >> 3, u = idx & 7;                                   \
            cpa16(base + M3_SB + n * 128 + ((u * 16) ^ ((n & 7) << 4)),      \
                  Bsrc + brow + (size_t)n * KD3_ + k0_ + u * 8);             \
        }                                                                    \
        CPA_COMMIT();                                                        \
    }

    M3_LOAD(0, 0);
    M3_LOAD(1, 1);

    for (int chunk = 0; chunk < 9; chunk++) {
        if (chunk == 8) CPA_WAIT(0); else CPA_WAIT(1);
        __syncthreads();
        const int st = chunk & 1;
        const uint32_t abase = sb + st * M3_STG + M3_SA;
        const uint32_t bbase = sb + st * M3_STG + M3_SB;
#pragma unroll
        for (int ksi = 0; ksi < 4; ksi++) {
            uint32_t a[2][4];
#pragma unroll
            for (int mt = 0; mt < 2; mt++) {
                int m = m_w + mt * 16 + (lane & 15);
                uint32_t addr = abase + m * 128 +
                    (((uint32_t)(ksi * 32 + (lane >> 4) * 16)) ^ ((m & 7) << 4));
                ldmx4(a[mt], addr);
            }
            uint32_t b[4][4];
#pragma unroll
            for (int pr = 0; pr < 4; pr++) {
                int n = n_w + pr * 16 + (lane >> 4) * 8 + (lane & 7);
                uint32_t addr = bbase + n * 128 +
                    (((uint32_t)(ksi * 32 + ((lane >> 3) & 1) * 16)) ^ ((n & 7) << 4));
                ldmx4(b[pr], addr);
            }
#pragma unroll
            for (int mt = 0; mt < 2; mt++)
#pragma unroll
                for (int nt = 0; nt < 8; nt++)
                    mma_bf16(d[mt][nt], a[mt], &b[nt >> 1][(nt & 1) * 2]);
        }
        __syncthreads();
        if (chunk + 2 < 9) M3_LOAD(chunk + 2, st);
    }

    const int qrow = lane >> 2, qcol = (lane & 3) * 2;
#pragma unroll
    for (int mt = 0; mt < 2; mt++) {
#pragma unroll
        for (int half = 0; half < 2; half++) {
            int m = m0 + m_w + mt * 16 + half * 8 + qrow;
            float sc = gamma[m] * rsqrtf(var[m] + 1e-5f);
            float bi = beta[m] - mean[m] * sc;
            float* Cp = out + ((size_t)bt * CS_ + m) * N1_ + nb + n_w;
#pragma unroll
            for (int nt = 0; nt < 8; nt++) {
                float x = fmaxf(d[mt][nt][half * 2]     * sc + bi, 0.f);
                float y = fmaxf(d[mt][nt][half * 2 + 1] * sc + bi, 0.f);
                *(float2*)&Cp[nt * 8 + qcol] = make_float2(x, y);
            }
        }
    }
}

// ---------------------------------------------------------------------------
extern "C" void kernel_launch(void* const* d_in, const int* in_sizes, int n_in,
                              void* d_out, int out_size)
{
    const float* xyzs   = (const float*)d_in[0];
    const float* oxyzs  = (const float*)d_in[1];
    const float* feats  = (const float*)d_in[2];
    const float* ofeats = (const float*)d_in[3];
    const float* Wt0    = (const float*)d_in[4];
    const float* Wt1    = (const float*)d_in[5];
    const float* Ws     = (const float*)d_in[6];
    const float* gamma  = (const float*)d_in[7];
    const float* beta   = (const float*)d_in[8];
    const float* mean   = (const float*)d_in[9];
    const float* var    = (const float*)d_in[10];

    const int NEWF = B_ * L1_ * CS_ * N1_;
    int ofs = out_size - NEWF;
    float* outF = (float*)d_out;
    if (ofs > 0) {
        cudaMemcpyAsync(d_out, d_in[1], (size_t)ofs * sizeof(float),
                        cudaMemcpyDeviceToDevice, 0);
        outF += ofs;
    }

    cudaFuncSetAttribute(k_hgemm_f, cudaFuncAttributeMaxDynamicSharedMemorySize,
                         HG_TOTAL);
    cudaFuncSetAttribute(k_mma3, cudaFuncAttributeMaxDynamicSharedMemorySize,
                         M3_TOTAL);

    k_prep<<<PREP_W + PREP_F + PREP_OF + PREP_SS + PREP_SQ, 256>>>(
        Wt0, Wt1, Ws, feats, ofeats, xyzs, oxyzs);            // kernel 1
    k_hgemm_f<<<dim3(16, 1, 24), 256, HG_TOTAL>>>();          // kernel 2
    k_knn_interp<<<dim3(32, 18), 256>>>();                    // kernel 3
    k_mma3<<<dim3(64, 2, 18), 256, M3_TOTAL>>>(gamma, beta, mean, var, outF);
}